// round 15
// baseline (speedup 1.0000x reference)
#include <cuda_runtime.h>

// FullyConnectedTensorProduct: B=2^20, MUL=8, DIM=32, 4 paths of 8x8x8.
// R15: R13's scalar A-forming (cheap encoding: no mov.b64 pack/unpack) +
// R14's interleaved GEMM1/GEMM2 mainloop (5 independent MMA chains per kk).
// Weights paired (b0,b1) in smem (LDS.64); EPITCH=68 staging; raw-bit tf32 A.

typedef unsigned int u32;

#define ALPHA_F     0.08838834764831845f   /* 1/sqrt(128) */
#define INV_SQRT3_F 0.5773502691896258f
#define EPITCH 68

static __device__ __forceinline__ u32 cvt_tf32(float f) {
    u32 r;
    asm("cvt.rna.tf32.f32 %0, %1;" : "=r"(r) : "f"(f));
    return r;
}
static __device__ __forceinline__ u32 tf32_raw(float f) {
    return __float_as_uint(f);
}

static __device__ __forceinline__ void mma_tf32(float c[4],
        u32 a0, u32 a1, u32 a2, u32 a3, uint2 wv)
{
    asm("mma.sync.aligned.m16n8k8.row.col.f32.tf32.tf32.f32 "
        "{%0,%1,%2,%3}, {%4,%5,%6,%7}, {%8,%9}, {%0,%1,%2,%3};"
        : "+f"(c[0]), "+f"(c[1]), "+f"(c[2]), "+f"(c[3])
        : "r"(a0), "r"(a1), "r"(a2), "r"(a3), "r"(wv.x), "r"(wv.y));
}

__global__ __launch_bounds__(128, 4)
void fctp_kernel(const float* __restrict__ x1,
                 const float* __restrict__ x2,
                 const float* __restrict__ wt,
                 float* __restrict__ out)
{
    extern __shared__ __align__(16) float smem[];
    uint2* wsp = (uint2*)smem;        // 1024 pairs (b0,b1) per (kk,t,g)
    float* st  = smem + 2048;         // 128 * EPITCH staging

    const int tid = threadIdx.x;
    const size_t eBase = (size_t)blockIdx.x * 128;

    // ---- stage weights paired: float pos i = kk*64 + (t*8+g)*2 + j,
    //      src col c = kk*8 + t + 4*j, src idx = c*8 + g. INV_SQRT3 on W1.
#pragma unroll
    for (int c = 0; c < 16; c++) {
        int i  = tid + c * 128;
        int kk = i >> 6;
        int p  = (i >> 1) & 31;
        int j  = i & 1;
        int t_ = p >> 3, g_ = p & 7;
        int src = (kk * 8 + t_ + 4 * j) * 8 + g_;
        float s = ((src >> 9) == 1) ? INV_SQRT3_F : 1.0f;
        ((u32*)smem)[i] = cvt_tf32(__ldg(wt + src) * s);
    }

    // ---- stage inputs (STS.128): x1*ALPHA at [0..31], x2 at [32..63] ----
    {
        const float4* g1 = (const float4*)(x1 + eBase * 32);
        const float4* g2 = (const float4*)(x2 + eBase * 32);
#pragma unroll
        for (int c = 0; c < 8; c++) {
            int lin = tid + c * 128;
            int e = lin >> 3, j = (lin & 7) << 2;
            float4 a = g1[lin];
            a.x *= ALPHA_F; a.y *= ALPHA_F; a.z *= ALPHA_F; a.w *= ALPHA_F;
            *(float4*)(st + e * EPITCH + j) = a;
            float4 b = g2[lin];
            *(float4*)(st + e * EPITCH + 32 + j) = b;
        }
    }
    __syncthreads();

    const int lane = tid & 31;
    const int g = lane >> 2;
    const int t = lane & 3;
    const int wBase = (tid >> 5) * 32;
    const int wIdx = t * 8 + g;

#pragma unroll
    for (int rb = 0; rb < 2; rb++) {
        float* Rlo = st + (wBase + rb * 16 + g) * EPITCH;
        float* Rhi = Rlo + 8 * EPITCH;

        // ---- vector input cache (scalar floats, no packing) ----
        float4 s1lq0 = *(const float4*)(Rlo + 0);
        float4 s1lq1 = *(const float4*)(Rlo + 4);
        float4 s1hq0 = *(const float4*)(Rhi + 0);
        float4 s1hq1 = *(const float4*)(Rhi + 4);
        float s1l[8] = {s1lq0.x, s1lq0.y, s1lq0.z, s1lq0.w,
                        s1lq1.x, s1lq1.y, s1lq1.z, s1lq1.w};
        float s1h[8] = {s1hq0.x, s1hq0.y, s1hq0.z, s1hq0.w,
                        s1hq1.x, s1hq1.y, s1hq1.z, s1hq1.w};
        float v1l[24], v1h[24];
#pragma unroll
        for (int q = 0; q < 6; q++) {
            float4 a = *(const float4*)(Rlo + 8 + 4 * q);
            v1l[4*q+0] = a.x; v1l[4*q+1] = a.y; v1l[4*q+2] = a.z; v1l[4*q+3] = a.w;
            float4 b = *(const float4*)(Rhi + 8 + 4 * q);
            v1h[4*q+0] = b.x; v1h[4*q+1] = b.y; v1h[4*q+2] = b.z; v1h[4*q+3] = b.w;
        }
        float s2l[2], s2h[2], v2l[2][3], v2h[2][3];
#pragma unroll
        for (int j = 0; j < 2; j++) {
            int v = t + 4 * j;
            s2l[j] = Rlo[32 + v];
            s2h[j] = Rhi[32 + v];
#pragma unroll
            for (int k = 0; k < 3; k++) {
                v2l[j][k] = Rlo[40 + v * 3 + k];
                v2h[j][k] = Rhi[40 + v * 3 + k];
            }
        }

        float C0a[4] = {0.f, 0.f, 0.f, 0.f};
        float C0b[4] = {0.f, 0.f, 0.f, 0.f};
        float C1[3][4] = {};

        // ---- kk 0..7: s1-based halves of GEMM1 & GEMM2, interleaved ----
#pragma unroll
        for (int kk = 0; kk < 8; kk++) {
            uint2 wv1 = wsp[kk * 32 + wIdx];
            uint2 wv2 = wsp[(16 + kk) * 32 + wIdx];
            mma_tf32(C0a,
                     tf32_raw(s1l[kk] * s2l[0]), tf32_raw(s1h[kk] * s2h[0]),
                     tf32_raw(s1l[kk] * s2l[1]), tf32_raw(s1h[kk] * s2h[1]),
                     wv1);
#pragma unroll
            for (int k = 0; k < 3; k++)
                mma_tf32(C1[k],
                         tf32_raw(s1l[kk] * v2l[0][k]), tf32_raw(s1h[kk] * v2h[0][k]),
                         tf32_raw(s1l[kk] * v2l[1][k]), tf32_raw(s1h[kk] * v2h[1][k]),
                         wv2);
        }

        // ---- kk 8..15: v1-based halves, interleaved ----
#pragma unroll
        for (int kk = 8; kk < 16; kk++) {
            int u = kk - 8;
            uint2 wv1 = wsp[kk * 32 + wIdx];
            uint2 wv2 = wsp[(16 + kk) * 32 + wIdx];
            u32 a0 = tf32_raw(v1l[u*3+0] * v2l[0][0] + v1l[u*3+1] * v2l[0][1]
                              + v1l[u*3+2] * v2l[0][2]);
            u32 a1 = tf32_raw(v1h[u*3+0] * v2h[0][0] + v1h[u*3+1] * v2h[0][1]
                              + v1h[u*3+2] * v2h[0][2]);
            u32 a2 = tf32_raw(v1l[u*3+0] * v2l[1][0] + v1l[u*3+1] * v2l[1][1]
                              + v1l[u*3+2] * v2l[1][2]);
            u32 a3 = tf32_raw(v1h[u*3+0] * v2h[1][0] + v1h[u*3+1] * v2h[1][1]
                              + v1h[u*3+2] * v2h[1][2]);
            mma_tf32(C0b, a0, a1, a2, a3, wv1);
#pragma unroll
            for (int k = 0; k < 3; k++)
                mma_tf32(C1[k],
                         tf32_raw(v1l[u*3+k] * s2l[0]), tf32_raw(v1h[u*3+k] * s2h[0]),
                         tf32_raw(v1l[u*3+k] * s2l[1]), tf32_raw(v1h[u*3+k] * s2h[1]),
                         wv2);
        }

        // ---- vector stores into own staging rows ----
        // C layout: c0:(g,2t) c1:(g,2t+1) c2:(g+8,2t) c3:(g+8,2t+1)
        *(float2*)(Rlo + 2 * t) = make_float2(C0a[0] + C0b[0], C0a[1] + C0b[1]);
        *(float2*)(Rhi + 2 * t) = make_float2(C0a[2] + C0b[2], C0a[3] + C0b[3]);
        *(float2*)(Rlo + 8 + 6 * t)     = make_float2(C1[0][0], C1[1][0]);
        *(float2*)(Rlo + 8 + 6 * t + 2) = make_float2(C1[2][0], C1[0][1]);
        *(float2*)(Rlo + 8 + 6 * t + 4) = make_float2(C1[1][1], C1[2][1]);
        *(float2*)(Rhi + 8 + 6 * t)     = make_float2(C1[0][2], C1[1][2]);
        *(float2*)(Rhi + 8 + 6 * t + 2) = make_float2(C1[2][2], C1[0][3]);
        *(float2*)(Rhi + 8 + 6 * t + 4) = make_float2(C1[1][3], C1[2][3]);
    }

    __syncthreads();

    // ---- coalesced drain (LDS.128 -> STG.128) ----
    {
        float4* go = (float4*)(out + eBase * 32);
#pragma unroll
        for (int c = 0; c < 8; c++) {
            int lin = tid + c * 128;
            int e = lin >> 3, j = (lin & 7) << 2;
            go[lin] = *(const float4*)(st + e * EPITCH + j);
        }
    }
}

extern "C" void kernel_launch(void* const* d_in, const int* in_sizes, int n_in,
                              void* d_out, int out_size)
{
    const float* x1 = (const float*)d_in[0];
    const float* x2 = (const float*)d_in[1];
    const float* wt = (const float*)d_in[2];
    float* out = (float*)d_out;

    int nelem  = out_size / 32;                            // 2^20
    int blocks = nelem / 128;                              // 128 elements/block
    size_t smem = (2048 + 128 * EPITCH) * sizeof(float);   // 43008 B

    static bool attr_set = false;
    if (!attr_set) {
        cudaFuncSetAttribute(fctp_kernel,
                             cudaFuncAttributeMaxDynamicSharedMemorySize,
                             (int)smem);
        attr_set = true;
    }
    fctp_kernel<<<blocks, 128, smem>>>(x1, x2, wt, out);
}